// round 16
// baseline (speedup 1.0000x reference)
#include <cuda_runtime.h>
#include <cuda_fp16.h>
#include <cstdint>

#define B_ 16
#define C_ 256
#define S_ 512
#define P_ 66
#define STYLE_SCALE 0.03125f
#define EPS_ 1e-8f
#define XT_ELEMS ((size_t)B_ * P_ * P_ * C_)

// ---------------- device scratch ----------------
__device__ __half g_xt[XT_ELEMS];            // style1-scaled x, NHWC padded, fp16
__device__ __half g_ht[XT_ELEMS];            // style2-scaled h, NHWC padded, fp16
__device__ __half g_wf[2][9][16][C_][16];    // weights fp16 [conv][tap][cin16][cout][cin&15]
__device__ float  g_wsq[2][C_][C_];
__device__ float  g_style[2][B_][C_];
__device__ float  g_demod[2][B_][C_];

// ---------------- PTX helpers ----------------
__device__ __forceinline__ uint32_t smem_u32(const void* p) {
    uint32_t a;
    asm("{ .reg .u64 t; cvta.to.shared.u64 t, %1; cvt.u32.u64 %0, t; }" : "=r"(a) : "l"(p));
    return a;
}
__device__ __forceinline__ void cp16(uint32_t s, const void* g) {
    asm volatile("cp.async.cg.shared.global [%0], [%1], 16;" :: "r"(s), "l"(g));
}
__device__ __forceinline__ void cp_commit() { asm volatile("cp.async.commit_group;" ::: "memory"); }
__device__ __forceinline__ void cp_wait0()  { asm volatile("cp.async.wait_group 0;" ::: "memory"); }
__device__ __forceinline__ void ldmx4(uint32_t* r, uint32_t a) {
    asm volatile("ldmatrix.sync.aligned.m8n8.x4.shared.b16 {%0,%1,%2,%3}, [%4];"
                 : "=r"(r[0]), "=r"(r[1]), "=r"(r[2]), "=r"(r[3]) : "r"(a));
}
__device__ __forceinline__ void ldmx2(uint32_t* r, uint32_t a) {
    asm volatile("ldmatrix.sync.aligned.m8n8.x2.shared.b16 {%0,%1}, [%2];"
                 : "=r"(r[0]), "=r"(r[1]) : "r"(a));
}
__device__ __forceinline__ void mma16816(float* d, const uint32_t* a, const uint32_t* b) {
    asm volatile(
        "mma.sync.aligned.m16n8k16.row.col.f32.f16.f16.f32 "
        "{%0,%1,%2,%3}, {%4,%5,%6,%7}, {%8,%9}, {%0,%1,%2,%3};"
        : "+f"(d[0]), "+f"(d[1]), "+f"(d[2]), "+f"(d[3])
        : "r"(a[0]), "r"(a[1]), "r"(a[2]), "r"(a[3]), "r"(b[0]), "r"(b[1]));
}

// ================= prep1: wprep (blocks 0..511) + style (blocks 512..1535) ==========
#define PREP1_WBLOCKS 512     // 2*C*C / 256
#define PREP1_BLOCKS  1536
__global__ void prep1_kernel(const float* __restrict__ w1, const float* __restrict__ w2,
                             const float* __restrict__ w1v, const float* __restrict__ w2v,
                             const float* __restrict__ s1w, const float* __restrict__ s1b,
                             const float* __restrict__ s2w, const float* __restrict__ s2b) {
    if (blockIdx.x < PREP1_WBLOCKS) {
        int idx = blockIdx.x * 256 + threadIdx.x;     // 2*C*C
        int cv = idx >> 16, co = (idx >> 8) & 255, ci = idx & 255;
        const float* w = cv ? w2 : w1;
        float sq = 0.f;
        #pragma unroll
        for (int k = 0; k < 9; k++) {
            float v = w[(co * C_ + ci) * 9 + k];
            sq += v * v;
            g_wf[cv][k][ci >> 4][co][ci & 15] = __float2half(v);
        }
        g_wsq[cv][co][ci] = sq;
    } else {
        int gw = (blockIdx.x - PREP1_WBLOCKS) * 8 + (threadIdx.x >> 5);   // 2*B*C warps
        int lane = threadIdx.x & 31;
        int cv = gw >> 12, b = (gw >> 8) & 15, c = gw & 255;
        const float* wv = (cv ? w2v : w1v) + b * S_;
        const float* sr = (cv ? s2w : s1w) + c * S_;
        float sum = 0.f;
        #pragma unroll 4
        for (int s = lane; s < S_; s += 32) sum += wv[s] * sr[s];
        #pragma unroll
        for (int o = 16; o > 0; o >>= 1) sum += __shfl_down_sync(0xffffffffu, sum, o);
        if (lane == 0) g_style[cv][b][c] = sum * STYLE_SCALE + (cv ? s2b : s1b)[c];
    }
}

// ========= prep2: xprep (0..4095) + halo (4096..8255) + demod (8256..9279) ==========
#define PREP2_XBLOCKS 4096
#define PREP2_HBLOCKS 4160    // ceil(B*260*C / 256)
#define PREP2_BLOCKS  (PREP2_XBLOCKS + PREP2_HBLOCKS + 1024)
__global__ void prep2_kernel(const float* __restrict__ x) {
    __shared__ float t[64][65];
    __shared__ float st[64];
    const int tid = threadIdx.x;
    if (blockIdx.x < PREP2_XBLOCKS) {
        // ---- xprep: x (NCHW fp32) -> style1-scaled padded NHWC fp16 ----
        int blk = blockIdx.x;
        int c0 = (blk & 3) << 6, py = (blk >> 2) & 63, b = blk >> 8;
        if (tid < 64) st[tid] = g_style[0][b][c0 + tid];
        // float4 loads: 64 ci x 16 float4 per row = 1024 float4 -> 4 per thread
        {
            int ci0 = tid >> 4, f4 = tid & 15;
            #pragma unroll
            for (int i = 0; i < 4; i++) {
                int ci = ci0 + (i << 4);
                float4 v = *reinterpret_cast<const float4*>(
                    x + (((size_t)b * C_ + c0 + ci) << 12) + (py << 6) + (f4 << 2));
                t[ci][(f4 << 2) + 0] = v.x;
                t[ci][(f4 << 2) + 1] = v.y;
                t[ci][(f4 << 2) + 2] = v.z;
                t[ci][(f4 << 2) + 3] = v.w;
            }
        }
        __syncthreads();
        #pragma unroll 4
        for (int i = 0; i < 16; i++) {
            int px = (i << 2) + (tid >> 6), ci = tid & 63;
            float v = t[ci][px] * st[ci];
            size_t a = (((size_t)b * P_ + py + 1) * P_ + px + 1) * C_ + c0 + ci;
            g_xt[a] = __float2half(v);
        }
    } else if (blockIdx.x < PREP2_XBLOCKS + PREP2_HBLOCKS) {
        // ---- halo ring zeroing for both padded buffers ----
        int e = (blockIdx.x - PREP2_XBLOCKS) * 256 + tid;
        if (e >= B_ * 260 * C_) return;
        int ci = e & 255, tt = e >> 8, i = tt % 260, b = tt / 260;
        int py, px;
        if (i < 66)       { py = 0;       px = i; }
        else if (i < 132) { py = 65;      px = i - 66; }
        else if (i < 196) { py = i - 131; px = 0; }
        else              { py = i - 195; px = 65; }
        size_t a = (((size_t)b * P_ + py) * P_ + px) * C_ + ci;
        g_xt[a] = __float2half(0.f);
        g_ht[a] = __float2half(0.f);
    } else {
        // ---- demod ----
        int gw = (blockIdx.x - PREP2_XBLOCKS - PREP2_HBLOCKS) * 8 + (tid >> 5);
        int lane = tid & 31;
        int cv = gw >> 12, b = (gw >> 8) & 15, co = gw & 255;
        float sum = 0.f;
        #pragma unroll 4
        for (int ci = lane; ci < C_; ci += 32) {
            float s = g_style[cv][b][ci];
            sum += s * s * g_wsq[cv][co][ci];
        }
        #pragma unroll
        for (int o = 16; o > 0; o >>= 1) sum += __shfl_down_sync(0xffffffffu, sum, o);
        if (lane == 0) g_demod[cv][b][co] = rsqrtf(sum + EPS_);
    }
}

// ---------------- main conv: implicit GEMM, tap-reuse + dx-shuffle, occ 2 ----------------
// CTA: M=128 couts x N=128 px (2 image rows). Stage = cin16 chunk: B slab of
// 4 haloed rows x 66 px (8448B) + A 9 taps x 128 co (36864B). 16 stages, 2 slots.
// B fragments loaded ONCE per dy at aligned px grid; dx=1,2 variants synthesized
// by lane shuffles (bitwise-identical to shifted ldmatrix) -> B LDSM traffic /2.7.
#define SLOT_B 8448
#define SLOT_A 36864
#define SLOT_BYTES (SLOT_B + SLOT_A)      // 45312
#define NSLOT 2
#define SMEM_CONV (NSLOT * SLOT_BYTES)    // 90624
#define NSTAGE 16

__device__ __forceinline__ uint32_t swz(int unit32, int half16) {
    return (uint32_t)((unit32 * 32 + half16) ^ (((unit32 >> 2) & 1) << 4));
}

__global__ __launch_bounds__(256, 2)
void conv_hmma_kernel(const __half* __restrict__ xt, int wsel,
                      const float* __restrict__ nw,
                      const float* __restrict__ noise, int mode,
                      __half* __restrict__ o_h, float* __restrict__ outp) {
    extern __shared__ __align__(128) char smem_raw[];
    const uint32_t sb = smem_u32(smem_raw);

    const int tid = threadIdx.x;
    const int wid = tid >> 5, lane = tid & 31;
    const int warp_m = wid & 3, warp_n = wid >> 2;
    const int n0 = blockIdx.x << 7;
    const int co0 = blockIdx.y << 7;
    const int b = blockIdx.z;
    const int r0 = blockIdx.x << 1;

    const int a_min  = (lane & 7) + ((lane >> 3) & 1) * 8;
    const int a_koff = (lane >> 4) << 4;
    const int b_nin  = ((lane >> 4) << 3) + (lane & 7);
    const int b_koff = ((lane >> 3) & 1) << 4;
    const int l4 = (lane + 4) & 31;       // dx=1 source lane
    const int l8 = (lane + 8) & 31;       // dx=2 source lane
    const bool p28 = lane < 28;
    const bool p24 = lane < 24;

    float acc[2][8][4];
    #pragma unroll
    for (int i = 0; i < 2; i++)
        #pragma unroll
        for (int j = 0; j < 8; j++)
            #pragma unroll
            for (int r = 0; r < 4; r++) acc[i][j][r] = 0.f;

    auto load_stage = [&](int s) {
        if (s < NSTAGE) {
            const uint32_t slot = sb + (s & 1) * SLOT_BYTES;
            const int cin0 = s << 4;
            #pragma unroll
            for (int i = tid; i < 528; i += 256) {
                int row = i / 132, rem = i - row * 132;
                int px = rem >> 1, u = rem & 1;
                cp16(slot + row * 2112 + swz(px, u << 4),
                     xt + ((((size_t)b * P_ + r0 + row) * P_ + px) << 8) + cin0 + (u << 3));
            }
            const __half* wbase = &g_wf[wsel][0][s][co0][0];
            #pragma unroll
            for (int i = tid; i < 2304; i += 256) {
                int tap = i >> 8, rem = i & 255;
                int co = rem >> 1, u = rem & 1;
                cp16(slot + SLOT_B + tap * 4096 + swz(co, u << 4),
                     wbase + (size_t)tap * (16 * C_ * 16) + co * 16 + u * 8);
            }
        }
        cp_commit();
    };

    load_stage(0);

    #pragma unroll 1
    for (int s = 0; s < NSTAGE; s++) {
        cp_wait0();
        __syncthreads();
        load_stage(s + 1);
        const uint32_t slot = sb + (s & 1) * SLOT_BYTES;
        const uint32_t aslot = slot + SLOT_B;

        #pragma unroll
        for (int dy = 0; dy < 3; dy++) {
            const uint32_t rowbase = slot + (warp_n + dy) * 2112;

            // aligned base fragments: 9 n-frags covering px 0..71 of this row
            uint32_t base[9][2];
            #pragma unroll
            for (int g = 0; g < 4; g++) {
                uint32_t r[4];
                ldmx4(r, rowbase + swz(g * 16 + b_nin, b_koff));
                base[2 * g][0] = r[0];     base[2 * g][1] = r[1];
                base[2 * g + 1][0] = r[2]; base[2 * g + 1][1] = r[3];
            }
            {
                uint32_t r2[2];
                ldmx2(r2, rowbase + swz(64 + (lane & 7), (lane & 8) << 1));
                base[8][0] = r2[0]; base[8][1] = r2[1];
            }

            // ---- dx = 0 : direct ----
            {
                const int tap = dy * 3;
                uint32_t a[2][4];
                ldmx4(a[0], aslot + tap * 4096 + swz(warp_m * 32 + a_min, a_koff));
                ldmx4(a[1], aslot + tap * 4096 + swz(warp_m * 32 + 16 + a_min, a_koff));
                #pragma unroll
                for (int in = 0; in < 8; in++) {
                    mma16816(acc[0][in], a[0], base[in]);
                    mma16816(acc[1][in], a[1], base[in]);
                }
            }
            // ---- dx = 1 : lane+4 shuffle (spill at lane 28 from next frag) ----
            {
                const int tap = dy * 3 + 1;
                uint32_t a[2][4];
                ldmx4(a[0], aslot + tap * 4096 + swz(warp_m * 32 + a_min, a_koff));
                ldmx4(a[1], aslot + tap * 4096 + swz(warp_m * 32 + 16 + a_min, a_koff));
                #pragma unroll
                for (int in = 0; in < 8; in++) {
                    uint32_t b2[2];
                    #pragma unroll
                    for (int r = 0; r < 2; r++) {
                        uint32_t v = __shfl_sync(0xffffffffu, base[in][r], l4);
                        uint32_t w = __shfl_sync(0xffffffffu, base[in + 1][r], l4);
                        b2[r] = p28 ? v : w;
                    }
                    mma16816(acc[0][in], a[0], b2);
                    mma16816(acc[1][in], a[1], b2);
                }
            }
            // ---- dx = 2 : lane+8 shuffle (spill at lane 24 from next frag) ----
            {
                const int tap = dy * 3 + 2;
                uint32_t a[2][4];
                ldmx4(a[0], aslot + tap * 4096 + swz(warp_m * 32 + a_min, a_koff));
                ldmx4(a[1], aslot + tap * 4096 + swz(warp_m * 32 + 16 + a_min, a_koff));
                #pragma unroll
                for (int in = 0; in < 8; in++) {
                    uint32_t b2[2];
                    #pragma unroll
                    for (int r = 0; r < 2; r++) {
                        uint32_t v = __shfl_sync(0xffffffffu, base[in][r], l8);
                        uint32_t w = __shfl_sync(0xffffffffu, base[in + 1][r], l8);
                        b2[r] = p24 ? v : w;
                    }
                    mma16816(acc[0][in], a[0], b2);
                    mma16816(acc[1][in], a[1], b2);
                }
            }
        }
    }
    __syncthreads();   // protect smem reuse in epilogue

    // ---------------- epilogue ----------------
    const int qm = lane >> 2;
    const int qn = (lane & 3) << 1;

    if (mode == 1) {
        #pragma unroll
        for (int im = 0; im < 2; im++) {
            #pragma unroll
            for (int rr = 0; rr < 2; rr++) {
                const int m = co0 + warp_m * 32 + im * 16 + qm + rr * 8;
                const float dm = g_demod[wsel][b][m];
                const float nwv = nw[m];
                float* ob = outp + (((size_t)b << 8) + m) * 4096;
                #pragma unroll
                for (int in = 0; in < 8; in++) {
                    const int n = n0 + warp_n * 64 + in * 8 + qn;
                    float v0 = acc[im][in][rr * 2 + 0] * dm + nwv * noise[((size_t)b << 12) + n];
                    float v1 = acc[im][in][rr * 2 + 1] * dm + nwv * noise[((size_t)b << 12) + n + 1];
                    v0 = v0 > 0.f ? v0 : 0.2f * v0;
                    v1 = v1 > 0.f ? v1 : 0.2f * v1;
                    *reinterpret_cast<float2*>(ob + n) = make_float2(v0, v1);
                }
            }
        }
    } else {
        __half* hs = reinterpret_cast<__half*>(smem_raw);   // [128 n][stride 136]
        #pragma unroll
        for (int im = 0; im < 2; im++) {
            #pragma unroll
            for (int rr = 0; rr < 2; rr++) {
                const int ml = warp_m * 32 + im * 16 + qm + rr * 8;
                const int m = co0 + ml;
                const float dm = g_demod[wsel][b][m];
                const float nwv = nw[m];
                const float sty = g_style[1][b][m];
                #pragma unroll
                for (int in = 0; in < 8; in++) {
                    const int nl = warp_n * 64 + in * 8 + qn;
                    const int n = n0 + nl;
                    float v0 = acc[im][in][rr * 2 + 0] * dm + nwv * noise[((size_t)b << 12) + n];
                    float v1 = acc[im][in][rr * 2 + 1] * dm + nwv * noise[((size_t)b << 12) + n + 1];
                    v0 = (v0 > 0.f ? v0 : 0.2f * v0) * sty;
                    v1 = (v1 > 0.f ? v1 : 0.2f * v1) * sty;
                    hs[nl * 136 + ml] = __float2half(v0);
                    hs[(nl + 1) * 136 + ml] = __float2half(v1);
                }
            }
        }
        __syncthreads();
        const int nl = tid >> 1, half = tid & 1;
        const int pix = n0 + nl;
        const int py = (pix >> 6) + 1, px = (pix & 63) + 1;
        const uint4* src = reinterpret_cast<const uint4*>(hs + nl * 136 + half * 64);
        uint4* dst = reinterpret_cast<uint4*>(
            o_h + ((((size_t)b * P_ + py) * P_ + px) << 8) + co0 + half * 64);
        #pragma unroll
        for (int i = 0; i < 8; i++) dst[i] = src[i];
    }
}

// ---------------- launcher ----------------
extern "C" void kernel_launch(void* const* d_in, const int* in_sizes, int n_in,
                              void* d_out, int out_size) {
    const float* x       = (const float*)d_in[0];
    const float* w1      = (const float*)d_in[1];
    const float* w2      = (const float*)d_in[2];
    const float* noise1  = (const float*)d_in[3];
    const float* noise2  = (const float*)d_in[4];
    const float* s1_w    = (const float*)d_in[5];
    const float* s1_b    = (const float*)d_in[6];
    const float* conv1_w = (const float*)d_in[7];
    const float* nw1     = (const float*)d_in[8];
    const float* s2_w    = (const float*)d_in[9];
    const float* s2_b    = (const float*)d_in[10];
    const float* conv2_w = (const float*)d_in[11];
    const float* nw2     = (const float*)d_in[12];
    float* out = (float*)d_out;

    __half *p_xt, *p_ht;
    cudaGetSymbolAddress((void**)&p_xt, g_xt);
    cudaGetSymbolAddress((void**)&p_ht, g_ht);

    cudaFuncSetAttribute(conv_hmma_kernel,
                         cudaFuncAttributeMaxDynamicSharedMemorySize, SMEM_CONV);

    prep1_kernel<<<PREP1_BLOCKS, 256>>>(conv1_w, conv2_w, w1, w2,
                                        s1_w, s1_b, s2_w, s2_b);
    prep2_kernel<<<PREP2_BLOCKS, 256>>>(x);

    dim3 grid(32, 2, 16);
    conv_hmma_kernel<<<grid, 256, SMEM_CONV>>>(p_xt, 0, nw1, noise1, 0, p_ht, nullptr);
    conv_hmma_kernel<<<grid, 256, SMEM_CONV>>>(p_ht, 1, nw2, noise2, 1, nullptr, out);
}